// round 5
// baseline (speedup 1.0000x reference)
#include <cuda_runtime.h>
#include <cstdint>

// ---------------- problem constants ----------------
#define NMAX 100000
#define EMAX 600000
#define FIN  128
#define FHID 128
#define FOUT 64

// ---------------- scratch (static device globals; no allocs) ----------------
__device__ __align__(16) float g_hn[(size_t)NMAX * FHID];   // layer-1 GEMM out (pre-agg)
__device__ __align__(16) float g_x2[(size_t)NMAX * FHID];   // layer-2 GEMM out hn2 (pre-agg)
__device__ __align__(16) float g_dinv[NMAX];
__device__ int   g_count[NMAX];
__device__ int   g_offsets[NMAX + 1];
__device__ int   g_cursor[NMAX];
__device__ int   g_srcsorted[EMAX];
__device__ int   g_blocksums[128];

// ---------------- degree / CSR build ----------------
__global__ void k_zero_count(int n) {
    int i = blockIdx.x * blockDim.x + threadIdx.x;
    if (i < n) g_count[i] = 0;
}

// edge_index is int32, layout [2, E]: src = ei[e], dst = ei[E + e]
__global__ void k_hist(const int* __restrict__ ei, int n_edges, int n_nodes) {
    int e = blockIdx.x * blockDim.x + threadIdx.x;
    if (e < n_edges) {
        int d = ei[n_edges + e];
        if ((unsigned)d < (unsigned)n_nodes) atomicAdd(&g_count[d], 1);
    }
}

// scan phase A: per-block sum of 1024 counts
__global__ void k_scanA(int n) {
    __shared__ int s[256];
    int t = threadIdx.x;
    int base = blockIdx.x * 1024;
    int v = 0;
    #pragma unroll
    for (int k = 0; k < 4; k++) {
        int i = base + t * 4 + k;
        if (i < n) v += g_count[i];
    }
    s[t] = v;
    __syncthreads();
    for (int off = 128; off > 0; off >>= 1) {
        if (t < off) s[t] += s[t + off];
        __syncthreads();
    }
    if (t == 0) g_blocksums[blockIdx.x] = s[0];
}

// scan phase B: parallel exclusive scan of block sums (nb <= 128)
__global__ void k_scanB(int nb, int n_nodes, int n_edges) {
    __shared__ int s[128];
    int t = threadIdx.x;
    int v = (t < nb) ? g_blocksums[t] : 0;
    s[t] = v;
    __syncthreads();
    #pragma unroll
    for (int off = 1; off < 128; off <<= 1) {
        int x = (t >= off) ? s[t - off] : 0;
        __syncthreads();
        s[t] += x;
        __syncthreads();
    }
    if (t < nb) g_blocksums[t] = s[t] - v;   // exclusive
    if (t == 0) g_offsets[n_nodes] = n_edges;
}

// scan phase C: exclusive scan within block + offsets + cursor + dinv
__global__ void k_scanC(int n) {
    __shared__ int s[256];
    int t = threadIdx.x;
    int base = blockIdx.x * 1024;
    int vals[4];
    int tsum = 0;
    #pragma unroll
    for (int k = 0; k < 4; k++) {
        int i = base + t * 4 + k;
        vals[k] = (i < n) ? g_count[i] : 0;
        tsum += vals[k];
    }
    s[t] = tsum;
    __syncthreads();
    for (int off = 1; off < 256; off <<= 1) {
        int x = (t >= off) ? s[t - off] : 0;
        __syncthreads();
        s[t] += x;
        __syncthreads();
    }
    int texcl = s[t] - tsum + g_blocksums[blockIdx.x];
    int run = 0;
    #pragma unroll
    for (int k = 0; k < 4; k++) {
        int i = base + t * 4 + k;
        if (i < n) {
            int o = texcl + run;
            g_offsets[i] = o;
            g_cursor[i]  = o;
            g_dinv[i]    = rsqrtf((float)(vals[k] + 1));   // +1 self loop
        }
        run += vals[k];
    }
}

__global__ void k_fill(const int* __restrict__ ei, int n_edges, int n_nodes) {
    int e = blockIdx.x * blockDim.x + threadIdx.x;
    if (e < n_edges) {
        int srcv = ei[e];
        int d    = ei[n_edges + e];
        if ((unsigned)d < (unsigned)n_nodes && (unsigned)srcv < (unsigned)n_nodes) {
            int p = atomicAdd(&g_cursor[d], 1);
            g_srcsorted[p] = srcv;
        }
    }
}

// ---------------- TF32 helpers ----------------
__device__ __forceinline__ float to_tf32(float x) {
    uint32_t u;
    asm("cvt.rna.tf32.f32 %0, %1;" : "=r"(u) : "f"(x));
    return __uint_as_float(u);
}

__device__ __forceinline__ void mma_tf32(float c[4], const float a[4], float b0, float b1) {
    uint32_t const* A = reinterpret_cast<uint32_t const*>(a);
    uint32_t B0 = __float_as_uint(b0), B1 = __float_as_uint(b1);
    asm volatile(
        "mma.sync.aligned.m16n8k8.row.col.f32.tf32.tf32.f32 "
        "{%0,%1,%2,%3}, {%4,%5,%6,%7}, {%8,%9}, {%0,%1,%2,%3};"
        : "+f"(c[0]), "+f"(c[1]), "+f"(c[2]), "+f"(c[3])
        : "r"(A[0]), "r"(A[1]), "r"(A[2]), "r"(A[3]), "r"(B0), "r"(B1));
}

// ---------------- GEMM1: g_hn = dinv[m] * (X @ W1)  (tf32 mma) ----------------
// 128 rows x 128 cols per block, K=128 streamed in 32-chunks. 8 warps = 4(M) x 2(N).
__global__ void __launch_bounds__(256)
k_mma1(const float* __restrict__ A, const float* __restrict__ Bg, int M, int K) {
    const int BN = 128, KC = 32;
    const int APITCH = KC + 4;         // 36
    const int BPITCH = BN + 8;         // 136
    __shared__ float As[128 * APITCH];
    __shared__ float Bs[KC * BPITCH];

    int tid  = threadIdx.x;
    int warp = tid >> 5, lane = tid & 31;
    int wm = warp & 3, wn = warp >> 2;
    const int WNT = BN / 2, NF = WNT / 8;   // 64, 8
    int g = lane >> 2, tg = lane & 3;
    int row0 = blockIdx.x * 128;

    float acc[2][NF][4];
    #pragma unroll
    for (int i = 0; i < 2; i++)
        #pragma unroll
        for (int j = 0; j < NF; j++)
            #pragma unroll
            for (int q = 0; q < 4; q++) acc[i][j][q] = 0.0f;

    for (int k0 = 0; k0 < K; k0 += KC) {
        {   // stage A [128 x 32]
            int r = tid >> 3, c = (tid & 7) * 4;
            #pragma unroll
            for (int i = 0; i < 4; i++) {
                int rr = r + i * 32;
                float4 v = make_float4(0.f, 0.f, 0.f, 0.f);
                if (row0 + rr < M)
                    v = *reinterpret_cast<const float4*>(A + (size_t)(row0 + rr) * K + k0 + c);
                v.x = to_tf32(v.x); v.y = to_tf32(v.y);
                v.z = to_tf32(v.z); v.w = to_tf32(v.w);
                *reinterpret_cast<float4*>(&As[rr * APITCH + c]) = v;
            }
        }
        {   // stage B [32 x 128]
            int kr = tid >> 5, bc = (tid & 31) * 4;
            #pragma unroll
            for (int i = 0; i < 4; i++) {
                int kk = kr + i * 8;
                float4 v = *reinterpret_cast<const float4*>(Bg + (size_t)(k0 + kk) * BN + bc);
                v.x = to_tf32(v.x); v.y = to_tf32(v.y);
                v.z = to_tf32(v.z); v.w = to_tf32(v.w);
                *reinterpret_cast<float4*>(&Bs[kk * BPITCH + bc]) = v;
            }
        }
        __syncthreads();

        #pragma unroll
        for (int ks = 0; ks < KC; ks += 8) {
            float a[2][4];
            #pragma unroll
            for (int mf = 0; mf < 2; mf++) {
                int ar = wm * 32 + mf * 16;
                a[mf][0] = As[(ar + g)     * APITCH + ks + tg];
                a[mf][1] = As[(ar + g + 8) * APITCH + ks + tg];
                a[mf][2] = As[(ar + g)     * APITCH + ks + tg + 4];
                a[mf][3] = As[(ar + g + 8) * APITCH + ks + tg + 4];
            }
            #pragma unroll
            for (int nf = 0; nf < NF; nf++) {
                int bn0 = wn * WNT + nf * 8;
                float b0 = Bs[(ks + tg)     * BPITCH + bn0 + g];
                float b1 = Bs[(ks + tg + 4) * BPITCH + bn0 + g];
                #pragma unroll
                for (int mf = 0; mf < 2; mf++)
                    mma_tf32(acc[mf][nf], a[mf], b0, b1);
            }
        }
        __syncthreads();
    }

    #pragma unroll
    for (int mf = 0; mf < 2; mf++) {
        int r0 = row0 + wm * 32 + mf * 16 + g;
        int r1 = r0 + 8;
        float d0 = (r0 < M) ? g_dinv[r0] : 0.f;
        float d1 = (r1 < M) ? g_dinv[r1] : 0.f;
        #pragma unroll
        for (int nf = 0; nf < NF; nf++) {
            int cc = wn * WNT + nf * 8 + tg * 2;
            if (r0 < M) {
                g_hn[(size_t)r0 * BN + cc]     = acc[mf][nf][0] * d0;
                g_hn[(size_t)r0 * BN + cc + 1] = acc[mf][nf][1] * d0;
            }
            if (r1 < M) {
                g_hn[(size_t)r1 * BN + cc]     = acc[mf][nf][2] * d1;
                g_hn[(size_t)r1 * BN + cc + 1] = acc[mf][nf][3] * d1;
            }
        }
    }
}

// ---------------- fused: layer-1 aggregation + layer-2 GEMM ----------------
// Block = 128 nodes. Phase A: x2_tile[r] = relu(dinv*(hn[d]+sum hn[s]) + b1) -> smem (tf32)
// Phase B: g_x2[d, 0:64] = dinv[d] * (x2_tile @ W2)   (tf32 mma)
#define AG_APITCH 132         // 128 + 4
#define AG_BPITCH 72          // 64 + 8
#define AG_SMEM_BYTES ((128 * AG_APITCH + 128 * AG_BPITCH) * 4)

__global__ void __launch_bounds__(256)
k_agg_gemm2(const float* __restrict__ W2, const float* __restrict__ b1, int M) {
    extern __shared__ float sm[];
    float* As = sm;                          // [128][AG_APITCH]
    float* Bs = sm + 128 * AG_APITCH;        // [128][AG_BPITCH]

    int tid  = threadIdx.x;
    int warp = tid >> 5, lane = tid & 31;
    int row0 = blockIdx.x * 128;

    // ---- stage W2 [128 x 64] tf32 into Bs ----
    {
        int kr = tid >> 4, bc = (tid & 15) * 4;
        #pragma unroll
        for (int i = 0; i < 8; i++) {
            int kk = kr + i * 16;
            float4 v = *reinterpret_cast<const float4*>(W2 + (size_t)kk * 64 + bc);
            v.x = to_tf32(v.x); v.y = to_tf32(v.y);
            v.z = to_tf32(v.z); v.w = to_tf32(v.w);
            *reinterpret_cast<float4*>(&Bs[kk * AG_BPITCH + bc]) = v;
        }
    }

    // ---- phase A: aggregate 16 nodes per warp ----
    float4 bv = *reinterpret_cast<const float4*>(b1 + lane * 4);
    const float* hn = g_hn;
    for (int i = 0; i < 16; i++) {
        int r = warp * 16 + i;
        int d = row0 + r;
        float4 o = make_float4(0.f, 0.f, 0.f, 0.f);
        if (d < M) {
            float4 acc = *reinterpret_cast<const float4*>(hn + (size_t)d * 128 + lane * 4);
            float4 acc2 = make_float4(0.f, 0.f, 0.f, 0.f);
            int e = g_offsets[d], e1 = g_offsets[d + 1];
            for (; e + 4 <= e1; e += 4) {
                int s0 = g_srcsorted[e],     s1 = g_srcsorted[e + 1];
                int s2 = g_srcsorted[e + 2], s3 = g_srcsorted[e + 3];
                float4 v0 = *reinterpret_cast<const float4*>(hn + (size_t)s0 * 128 + lane * 4);
                float4 v1 = *reinterpret_cast<const float4*>(hn + (size_t)s1 * 128 + lane * 4);
                float4 v2 = *reinterpret_cast<const float4*>(hn + (size_t)s2 * 128 + lane * 4);
                float4 v3 = *reinterpret_cast<const float4*>(hn + (size_t)s3 * 128 + lane * 4);
                acc.x += v0.x; acc.y += v0.y; acc.z += v0.z; acc.w += v0.w;
                acc2.x += v1.x; acc2.y += v1.y; acc2.z += v1.z; acc2.w += v1.w;
                acc.x += v2.x; acc.y += v2.y; acc.z += v2.z; acc.w += v2.w;
                acc2.x += v3.x; acc2.y += v3.y; acc2.z += v3.z; acc2.w += v3.w;
            }
            for (; e < e1; e++) {
                int s = g_srcsorted[e];
                float4 v = *reinterpret_cast<const float4*>(hn + (size_t)s * 128 + lane * 4);
                acc.x += v.x; acc.y += v.y; acc.z += v.z; acc.w += v.w;
            }
            acc.x += acc2.x; acc.y += acc2.y; acc.z += acc2.z; acc.w += acc2.w;
            float dv = g_dinv[d];
            o.x = to_tf32(fmaxf(acc.x * dv + bv.x, 0.f));
            o.y = to_tf32(fmaxf(acc.y * dv + bv.y, 0.f));
            o.z = to_tf32(fmaxf(acc.z * dv + bv.z, 0.f));
            o.w = to_tf32(fmaxf(acc.w * dv + bv.w, 0.f));
        }
        *reinterpret_cast<float4*>(&As[r * AG_APITCH + lane * 4]) = o;
    }
    __syncthreads();

    // ---- phase B: 128x64x128 tf32 mma ----
    int wm = warp & 3, wn = warp >> 2;     // 4(M) x 2(N)
    const int WNT = 32, NF = 4;
    int g = lane >> 2, tg = lane & 3;

    float acc[2][NF][4];
    #pragma unroll
    for (int i = 0; i < 2; i++)
        #pragma unroll
        for (int j = 0; j < NF; j++)
            #pragma unroll
            for (int q = 0; q < 4; q++) acc[i][j][q] = 0.0f;

    #pragma unroll
    for (int ks = 0; ks < 128; ks += 8) {
        float a[2][4];
        #pragma unroll
        for (int mf = 0; mf < 2; mf++) {
            int ar = wm * 32 + mf * 16;
            a[mf][0] = As[(ar + g)     * AG_APITCH + ks + tg];
            a[mf][1] = As[(ar + g + 8) * AG_APITCH + ks + tg];
            a[mf][2] = As[(ar + g)     * AG_APITCH + ks + tg + 4];
            a[mf][3] = As[(ar + g + 8) * AG_APITCH + ks + tg + 4];
        }
        #pragma unroll
        for (int nf = 0; nf < NF; nf++) {
            int bn0 = wn * WNT + nf * 8;
            float b0 = Bs[(ks + tg)     * AG_BPITCH + bn0 + g];
            float b1v = Bs[(ks + tg + 4) * AG_BPITCH + bn0 + g];
            #pragma unroll
            for (int mf = 0; mf < 2; mf++)
                mma_tf32(acc[mf][nf], a[mf], b0, b1v);
        }
    }

    #pragma unroll
    for (int mf = 0; mf < 2; mf++) {
        int r0 = row0 + wm * 32 + mf * 16 + g;
        int r1 = r0 + 8;
        float d0 = (r0 < M) ? g_dinv[r0] : 0.f;
        float d1 = (r1 < M) ? g_dinv[r1] : 0.f;
        #pragma unroll
        for (int nf = 0; nf < NF; nf++) {
            int cc = wn * WNT + nf * 8 + tg * 2;
            if (r0 < M) {
                g_x2[(size_t)r0 * 64 + cc]     = acc[mf][nf][0] * d0;
                g_x2[(size_t)r0 * 64 + cc + 1] = acc[mf][nf][1] * d0;
            }
            if (r1 < M) {
                g_x2[(size_t)r1 * 64 + cc]     = acc[mf][nf][2] * d1;
                g_x2[(size_t)r1 * 64 + cc + 1] = acc[mf][nf][3] * d1;
            }
        }
    }
}

// ---------------- layer-2 aggregation: out = dinv*(hn2[d] + sum hn2[s]) + b2 ----------------
__global__ void k_agg64(const float* __restrict__ bias,
                        float* __restrict__ out, int n_nodes) {
    int warp = (blockIdx.x * blockDim.x + threadIdx.x) >> 5;
    int lane = threadIdx.x & 31;
    if (warp >= n_nodes) return;
    int d = warp;
    const float* hn = g_x2;
    float2 acc = *reinterpret_cast<const float2*>(hn + (size_t)d * 64 + lane * 2);
    float2 acc2 = make_float2(0.f, 0.f);
    int e = g_offsets[d], e1 = g_offsets[d + 1];
    for (; e + 4 <= e1; e += 4) {
        int s0 = g_srcsorted[e],     s1 = g_srcsorted[e + 1];
        int s2 = g_srcsorted[e + 2], s3 = g_srcsorted[e + 3];
        float2 v0 = *reinterpret_cast<const float2*>(hn + (size_t)s0 * 64 + lane * 2);
        float2 v1 = *reinterpret_cast<const float2*>(hn + (size_t)s1 * 64 + lane * 2);
        float2 v2 = *reinterpret_cast<const float2*>(hn + (size_t)s2 * 64 + lane * 2);
        float2 v3 = *reinterpret_cast<const float2*>(hn + (size_t)s3 * 64 + lane * 2);
        acc.x += v0.x; acc.y += v0.y;
        acc2.x += v1.x; acc2.y += v1.y;
        acc.x += v2.x; acc.y += v2.y;
        acc2.x += v3.x; acc2.y += v3.y;
    }
    for (; e < e1; e++) {
        int s = g_srcsorted[e];
        float2 v = *reinterpret_cast<const float2*>(hn + (size_t)s * 64 + lane * 2);
        acc.x += v.x; acc.y += v.y;
    }
    acc.x += acc2.x; acc.y += acc2.y;
    float dv = g_dinv[d];
    float2 bv = *reinterpret_cast<const float2*>(bias + lane * 2);
    float2 o;
    o.x = acc.x * dv + bv.x;
    o.y = acc.y * dv + bv.y;
    *reinterpret_cast<float2*>(out + (size_t)d * 64 + lane * 2) = o;
}

// ---------------- launch ----------------
extern "C" void kernel_launch(void* const* d_in, const int* in_sizes, int n_in,
                              void* d_out, int out_size) {
    const float* x  = (const float*)d_in[0];
    const int*   ei = (const int*)d_in[1];     // int32 [2, E]
    const float* W1 = (const float*)d_in[2];
    const float* b1 = (const float*)d_in[3];
    const float* W2 = (const float*)d_in[4];
    const float* b2 = (const float*)d_in[5];
    float* out = (float*)d_out;

    int n_nodes = in_sizes[0] / FIN;       // 100000
    int n_edges = in_sizes[1] / 2;         // 600000

    int nb_nodes = (n_nodes + 255) / 256;
    int nb_edges = (n_edges + 255) / 256;
    int nb_scan  = (n_nodes + 1023) / 1024;
    int nb_gemm  = (n_nodes + 127) / 128;
    int nb_agg   = (n_nodes * 32 + 255) / 256;

    static bool attr_set = false;
    if (!attr_set) {
        cudaFuncSetAttribute(k_agg_gemm2,
                             cudaFuncAttributeMaxDynamicSharedMemorySize,
                             AG_SMEM_BYTES);
        attr_set = true;
    }

    // ---- CSR build + degrees (6 launches) ----
    k_zero_count<<<nb_nodes, 256>>>(n_nodes);
    k_hist<<<nb_edges, 256>>>(ei, n_edges, n_nodes);
    k_scanA<<<nb_scan, 256>>>(n_nodes);
    k_scanB<<<1, 128>>>(nb_scan, n_nodes, n_edges);
    k_scanC<<<nb_scan, 256>>>(n_nodes);
    k_fill<<<nb_edges, 256>>>(ei, n_edges, n_nodes);

    // ---- layer 1 GEMM ----
    k_mma1<<<nb_gemm, 256>>>(x, W1, n_nodes, FIN);

    // ---- fused layer-1 aggregation + layer-2 GEMM ----
    k_agg_gemm2<<<nb_gemm, 256, AG_SMEM_BYTES>>>(W2, b1, n_nodes);

    // ---- layer-2 aggregation ----
    k_agg64<<<nb_agg, 256>>>(b2, out, n_nodes);
}

// round 6
// speedup vs baseline: 1.1443x; 1.1443x over previous
#include <cuda_runtime.h>
#include <cstdint>

// ---------------- problem constants ----------------
#define NMAX 100000
#define EMAX 600000
#define FIN  128
#define FHID 128
#define FOUT 64

// ---------------- scratch (static device globals; no allocs) ----------------
__device__ __align__(16) float g_hn[(size_t)NMAX * FHID];   // per-layer GEMM out (pre-agg)
__device__ __align__(16) float g_x2[(size_t)NMAX * FHID];   // layer-2 input
__device__ __align__(16) float g_dinv[NMAX];
__device__ int   g_count[NMAX];
__device__ int   g_offsets[NMAX + 1];
__device__ int   g_cursor[NMAX];
__device__ int   g_srcsorted[EMAX];
__device__ int   g_blocksums[128];

// ---------------- degree / CSR build ----------------
__global__ void k_zero_count(int n) {
    int i = blockIdx.x * blockDim.x + threadIdx.x;
    if (i < n) g_count[i] = 0;
}

// edge_index is int32, layout [2, E]: src = ei[e], dst = ei[E + e]
__global__ void k_hist(const int* __restrict__ ei, int n_edges, int n_nodes) {
    int e = blockIdx.x * blockDim.x + threadIdx.x;
    if (e < n_edges) {
        int d = ei[n_edges + e];
        if ((unsigned)d < (unsigned)n_nodes) atomicAdd(&g_count[d], 1);
    }
}

// scan phase A: per-block sum of 1024 counts
__global__ void k_scanA(int n) {
    __shared__ int s[256];
    int t = threadIdx.x;
    int base = blockIdx.x * 1024;
    int v = 0;
    #pragma unroll
    for (int k = 0; k < 4; k++) {
        int i = base + t * 4 + k;
        if (i < n) v += g_count[i];
    }
    s[t] = v;
    __syncthreads();
    for (int off = 128; off > 0; off >>= 1) {
        if (t < off) s[t] += s[t + off];
        __syncthreads();
    }
    if (t == 0) g_blocksums[blockIdx.x] = s[0];
}

// scan phase B: parallel exclusive scan of block sums (nb <= 128)
__global__ void k_scanB(int nb, int n_nodes, int n_edges) {
    __shared__ int s[128];
    int t = threadIdx.x;
    int v = (t < nb) ? g_blocksums[t] : 0;
    s[t] = v;
    __syncthreads();
    #pragma unroll
    for (int off = 1; off < 128; off <<= 1) {
        int x = (t >= off) ? s[t - off] : 0;
        __syncthreads();
        s[t] += x;
        __syncthreads();
    }
    if (t < nb) g_blocksums[t] = s[t] - v;   // exclusive
    if (t == 0) g_offsets[n_nodes] = n_edges;
}

// scan phase C: exclusive scan within block + offsets + cursor + dinv
__global__ void k_scanC(int n) {
    __shared__ int s[256];
    int t = threadIdx.x;
    int base = blockIdx.x * 1024;
    int vals[4];
    int tsum = 0;
    #pragma unroll
    for (int k = 0; k < 4; k++) {
        int i = base + t * 4 + k;
        vals[k] = (i < n) ? g_count[i] : 0;
        tsum += vals[k];
    }
    s[t] = tsum;
    __syncthreads();
    for (int off = 1; off < 256; off <<= 1) {
        int x = (t >= off) ? s[t - off] : 0;
        __syncthreads();
        s[t] += x;
        __syncthreads();
    }
    int texcl = s[t] - tsum + g_blocksums[blockIdx.x];
    int run = 0;
    #pragma unroll
    for (int k = 0; k < 4; k++) {
        int i = base + t * 4 + k;
        if (i < n) {
            int o = texcl + run;
            g_offsets[i] = o;
            g_cursor[i]  = o;
            g_dinv[i]    = rsqrtf((float)(vals[k] + 1));   // +1 self loop
        }
        run += vals[k];
    }
}

__global__ void k_fill(const int* __restrict__ ei, int n_edges, int n_nodes) {
    int e = blockIdx.x * blockDim.x + threadIdx.x;
    if (e < n_edges) {
        int srcv = ei[e];
        int d    = ei[n_edges + e];
        if ((unsigned)d < (unsigned)n_nodes && (unsigned)srcv < (unsigned)n_nodes) {
            int p = atomicAdd(&g_cursor[d], 1);
            g_srcsorted[p] = srcv;
        }
    }
}

// ---------------- TF32 helpers ----------------
__device__ __forceinline__ float to_tf32(float x) {
    uint32_t u;
    asm("cvt.rna.tf32.f32 %0, %1;" : "=r"(u) : "f"(x));
    return __uint_as_float(u);
}

__device__ __forceinline__ void mma_tf32(float c[4], const float a[4], float b0, float b1) {
    uint32_t const* A = reinterpret_cast<uint32_t const*>(a);
    uint32_t B0 = __float_as_uint(b0), B1 = __float_as_uint(b1);
    asm volatile(
        "mma.sync.aligned.m16n8k8.row.col.f32.tf32.tf32.f32 "
        "{%0,%1,%2,%3}, {%4,%5,%6,%7}, {%8,%9}, {%0,%1,%2,%3};"
        : "+f"(c[0]), "+f"(c[1]), "+f"(c[2]), "+f"(c[3])
        : "r"(A[0]), "r"(A[1]), "r"(A[2]), "r"(A[3]), "r"(B0), "r"(B1));
}

// ---------------- TF32 tensor-core GEMM with fused dinv epilogue ----------------
// g_hn[m,n] = g_dinv[m] * sum_k A[m,k]*B[k,n]
// A = external pointer (SRC=0) or g_x2 (SRC=1). BN = N (128 or 64), K multiple of 32.
template <int BN, int SRC>
__global__ void __launch_bounds__(256)
k_mma_dinv(const float* __restrict__ Aext, const float* __restrict__ Bg,
           int M, int K) {
    const float* __restrict__ A = (SRC == 0) ? Aext : g_x2;
    const int KC = 32;
    const int APITCH = KC + 4;        // 36
    const int BPITCH = BN + 8;
    __shared__ float As[128 * APITCH];
    __shared__ float Bs[KC * BPITCH];

    int tid  = threadIdx.x;
    int warp = tid >> 5, lane = tid & 31;
    int wm = warp & 3, wn = warp >> 2;
    const int WNT = BN / 2;
    const int NF  = WNT / 8;
    int g  = lane >> 2, tg = lane & 3;
    int row0 = blockIdx.x * 128;

    float acc[2][NF][4];
    #pragma unroll
    for (int i = 0; i < 2; i++)
        #pragma unroll
        for (int j = 0; j < NF; j++)
            #pragma unroll
            for (int q = 0; q < 4; q++) acc[i][j][q] = 0.0f;

    for (int k0 = 0; k0 < K; k0 += KC) {
        {   // stage A [128 x 32]
            int r = tid >> 3, c = (tid & 7) * 4;
            #pragma unroll
            for (int i = 0; i < 4; i++) {
                int rr = r + i * 32;
                float4 v = make_float4(0.f, 0.f, 0.f, 0.f);
                if (row0 + rr < M)
                    v = *reinterpret_cast<const float4*>(A + (size_t)(row0 + rr) * K + k0 + c);
                v.x = to_tf32(v.x); v.y = to_tf32(v.y);
                v.z = to_tf32(v.z); v.w = to_tf32(v.w);
                *reinterpret_cast<float4*>(&As[rr * APITCH + c]) = v;
            }
        }
        {   // stage B [32 x BN]
            const int TPR = BN / 4;
            int kr = tid / TPR, bc = (tid % TPR) * 4;
            const int KSTEP = 256 / TPR;
            #pragma unroll
            for (int i = 0; i < KC / KSTEP; i++) {
                int kk = kr + i * KSTEP;
                float4 v = *reinterpret_cast<const float4*>(Bg + (size_t)(k0 + kk) * BN + bc);
                v.x = to_tf32(v.x); v.y = to_tf32(v.y);
                v.z = to_tf32(v.z); v.w = to_tf32(v.w);
                *reinterpret_cast<float4*>(&Bs[kk * BPITCH + bc]) = v;
            }
        }
        __syncthreads();

        #pragma unroll
        for (int ks = 0; ks < KC; ks += 8) {
            float a[2][4];
            #pragma unroll
            for (int mf = 0; mf < 2; mf++) {
                int ar = wm * 32 + mf * 16;
                a[mf][0] = As[(ar + g)     * APITCH + ks + tg];
                a[mf][1] = As[(ar + g + 8) * APITCH + ks + tg];
                a[mf][2] = As[(ar + g)     * APITCH + ks + tg + 4];
                a[mf][3] = As[(ar + g + 8) * APITCH + ks + tg + 4];
            }
            #pragma unroll
            for (int nf = 0; nf < NF; nf++) {
                int bn0 = wn * WNT + nf * 8;
                float b0 = Bs[(ks + tg)     * BPITCH + bn0 + g];
                float b1 = Bs[(ks + tg + 4) * BPITCH + bn0 + g];
                #pragma unroll
                for (int mf = 0; mf < 2; mf++)
                    mma_tf32(acc[mf][nf], a[mf], b0, b1);
            }
        }
        __syncthreads();
    }

    #pragma unroll
    for (int mf = 0; mf < 2; mf++) {
        int r0 = row0 + wm * 32 + mf * 16 + g;
        int r1 = r0 + 8;
        float d0 = (r0 < M) ? g_dinv[r0] : 0.f;
        float d1 = (r1 < M) ? g_dinv[r1] : 0.f;
        #pragma unroll
        for (int nf = 0; nf < NF; nf++) {
            int cc = wn * WNT + nf * 8 + tg * 2;
            if (r0 < M) {
                g_hn[(size_t)r0 * BN + cc]     = acc[mf][nf][0] * d0;
                g_hn[(size_t)r0 * BN + cc + 1] = acc[mf][nf][1] * d0;
            }
            if (r1 < M) {
                g_hn[(size_t)r1 * BN + cc]     = acc[mf][nf][2] * d1;
                g_hn[(size_t)r1 * BN + cc + 1] = acc[mf][nf][3] * d1;
            }
        }
    }
}

// ---------------- aggregation: one warp per node, MLP-4 gathers ----------------
// x2[d] = relu( dinv[d]*(hn[d] + sum_{s in N(d)} hn[s]) + b1 )   (F=128)
__global__ void k_agg128(const float* __restrict__ bias, int n_nodes) {
    int warp = (blockIdx.x * blockDim.x + threadIdx.x) >> 5;
    int lane = threadIdx.x & 31;
    if (warp >= n_nodes) return;
    int d = warp;
    const float* hn = g_hn;
    float4 acc = *reinterpret_cast<const float4*>(hn + (size_t)d * 128 + lane * 4);
    float4 acc2 = make_float4(0.f, 0.f, 0.f, 0.f);
    int e = g_offsets[d], e1 = g_offsets[d + 1];
    for (; e + 4 <= e1; e += 4) {
        int s0 = g_srcsorted[e],     s1 = g_srcsorted[e + 1];
        int s2 = g_srcsorted[e + 2], s3 = g_srcsorted[e + 3];
        float4 v0 = *reinterpret_cast<const float4*>(hn + (size_t)s0 * 128 + lane * 4);
        float4 v1 = *reinterpret_cast<const float4*>(hn + (size_t)s1 * 128 + lane * 4);
        float4 v2 = *reinterpret_cast<const float4*>(hn + (size_t)s2 * 128 + lane * 4);
        float4 v3 = *reinterpret_cast<const float4*>(hn + (size_t)s3 * 128 + lane * 4);
        acc.x += v0.x; acc.y += v0.y; acc.z += v0.z; acc.w += v0.w;
        acc2.x += v1.x; acc2.y += v1.y; acc2.z += v1.z; acc2.w += v1.w;
        acc.x += v2.x; acc.y += v2.y; acc.z += v2.z; acc.w += v2.w;
        acc2.x += v3.x; acc2.y += v3.y; acc2.z += v3.z; acc2.w += v3.w;
    }
    for (; e < e1; e++) {
        int s = g_srcsorted[e];
        float4 v = *reinterpret_cast<const float4*>(hn + (size_t)s * 128 + lane * 4);
        acc.x += v.x; acc.y += v.y; acc.z += v.z; acc.w += v.w;
    }
    acc.x += acc2.x; acc.y += acc2.y; acc.z += acc2.z; acc.w += acc2.w;
    float dv = g_dinv[d];
    float4 bv = *reinterpret_cast<const float4*>(bias + lane * 4);
    float4 o;
    o.x = fmaxf(acc.x * dv + bv.x, 0.f);
    o.y = fmaxf(acc.y * dv + bv.y, 0.f);
    o.z = fmaxf(acc.z * dv + bv.z, 0.f);
    o.w = fmaxf(acc.w * dv + bv.w, 0.f);
    *reinterpret_cast<float4*>(g_x2 + (size_t)d * 128 + lane * 4) = o;
}

// out[d] = dinv[d]*(hn[d] + sum hn[s]) + b2   (F=64, no relu)
__global__ void k_agg64(const float* __restrict__ bias,
                        float* __restrict__ out, int n_nodes) {
    int warp = (blockIdx.x * blockDim.x + threadIdx.x) >> 5;
    int lane = threadIdx.x & 31;
    if (warp >= n_nodes) return;
    int d = warp;
    const float* hn = g_hn;
    float2 acc = *reinterpret_cast<const float2*>(hn + (size_t)d * 64 + lane * 2);
    float2 acc2 = make_float2(0.f, 0.f);
    int e = g_offsets[d], e1 = g_offsets[d + 1];
    for (; e + 4 <= e1; e += 4) {
        int s0 = g_srcsorted[e],     s1 = g_srcsorted[e + 1];
        int s2 = g_srcsorted[e + 2], s3 = g_srcsorted[e + 3];
        float2 v0 = *reinterpret_cast<const float2*>(hn + (size_t)s0 * 64 + lane * 2);
        float2 v1 = *reinterpret_cast<const float2*>(hn + (size_t)s1 * 64 + lane * 2);
        float2 v2 = *reinterpret_cast<const float2*>(hn + (size_t)s2 * 64 + lane * 2);
        float2 v3 = *reinterpret_cast<const float2*>(hn + (size_t)s3 * 64 + lane * 2);
        acc.x += v0.x; acc.y += v0.y;
        acc2.x += v1.x; acc2.y += v1.y;
        acc.x += v2.x; acc.y += v2.y;
        acc2.x += v3.x; acc2.y += v3.y;
    }
    for (; e < e1; e++) {
        int s = g_srcsorted[e];
        float2 v = *reinterpret_cast<const float2*>(hn + (size_t)s * 64 + lane * 2);
        acc.x += v.x; acc.y += v.y;
    }
    acc.x += acc2.x; acc.y += acc2.y;
    float dv = g_dinv[d];
    float2 bv = *reinterpret_cast<const float2*>(bias + lane * 2);
    float2 o;
    o.x = acc.x * dv + bv.x;
    o.y = acc.y * dv + bv.y;
    *reinterpret_cast<float2*>(out + (size_t)d * 64 + lane * 2) = o;
}

// ---------------- launch ----------------
extern "C" void kernel_launch(void* const* d_in, const int* in_sizes, int n_in,
                              void* d_out, int out_size) {
    const float* x  = (const float*)d_in[0];
    const int*   ei = (const int*)d_in[1];     // int32 [2, E]
    const float* W1 = (const float*)d_in[2];
    const float* b1 = (const float*)d_in[3];
    const float* W2 = (const float*)d_in[4];
    const float* b2 = (const float*)d_in[5];
    float* out = (float*)d_out;

    int n_nodes = in_sizes[0] / FIN;       // 100000
    int n_edges = in_sizes[1] / 2;         // 600000

    int nb_nodes = (n_nodes + 255) / 256;
    int nb_edges = (n_edges + 255) / 256;
    int nb_scan  = (n_nodes + 1023) / 1024;
    int nb_gemm  = (n_nodes + 127) / 128;
    int nb_agg   = (n_nodes * 32 + 255) / 256;

    // ---- CSR build + degrees (6 launches) ----
    k_zero_count<<<nb_nodes, 256>>>(n_nodes);
    k_hist<<<nb_edges, 256>>>(ei, n_edges, n_nodes);
    k_scanA<<<nb_scan, 256>>>(n_nodes);
    k_scanB<<<1, 128>>>(nb_scan, n_nodes, n_edges);
    k_scanC<<<nb_scan, 256>>>(n_nodes);
    k_fill<<<nb_edges, 256>>>(ei, n_edges, n_nodes);

    // ---- layer 1: hn = tf32(x@W1)*dinv ; x2 = relu(dinv*agg + b1) ----
    k_mma_dinv<FHID, 0><<<nb_gemm, 256>>>(x, W1, n_nodes, FIN);
    k_agg128<<<nb_agg, 256>>>(b1, n_nodes);

    // ---- layer 2: hn = tf32(x2@W2)*dinv ; out = dinv*agg + b2 ----
    k_mma_dinv<FOUT, 1><<<nb_gemm, 256>>>(nullptr, W2, n_nodes, FHID);
    k_agg64<<<nb_agg, 256>>>(b2, out, n_nodes);
}

// round 7
// speedup vs baseline: 1.1661x; 1.0190x over previous
#include <cuda_runtime.h>
#include <cstdint>

// ---------------- problem constants ----------------
#define NMAX 100000
#define EMAX 600000
#define FIN  128
#define FHID 128
#define FOUT 64

// ---------------- scratch (static device globals; no allocs) ----------------
__device__ __align__(16) float g_hn[(size_t)NMAX * FHID];   // per-layer GEMM out (pre-agg)
__device__ __align__(16) float g_x2[(size_t)NMAX * FHID];   // layer-2 input
__device__ __align__(16) float g_dinv[NMAX];
__device__ int   g_count[NMAX];
__device__ int   g_start[NMAX];
__device__ int   g_cursor[NMAX];
__device__ int   g_srcsorted[EMAX];
__device__ int   g_total;

// ---------------- degree / CSR build ----------------
__global__ void k_zero(int n) {
    int i = blockIdx.x * blockDim.x + threadIdx.x;
    if (i < n) g_count[i] = 0;
    if (i == 0) g_total = 0;
}

// edge_index is int32, layout [2, E]: src = ei[e], dst = ei[E + e]
__global__ void k_hist(const int* __restrict__ ei, int n_edges, int n_nodes) {
    int e = blockIdx.x * blockDim.x + threadIdx.x;
    if (e < n_edges) {
        int d = ei[n_edges + e];
        if ((unsigned)d < (unsigned)n_nodes) atomicAdd(&g_count[d], 1);
    }
}

// ONE-PASS order-free scan: per-block local prefix + atomic base grab.
// CSR segments need only be disjoint, not index-ordered, so block bases may be
// assigned in any order. Writes start/cursor/dinv.
__global__ void k_scan(int n) {
    __shared__ int s[256];
    __shared__ int base_sh;
    int t = threadIdx.x;
    int blk = blockIdx.x * 1024;
    int vals[4];
    int tsum = 0;
    #pragma unroll
    for (int k = 0; k < 4; k++) {
        int i = blk + t * 4 + k;
        vals[k] = (i < n) ? g_count[i] : 0;
        tsum += vals[k];
    }
    s[t] = tsum;
    __syncthreads();
    // Hillis-Steele inclusive scan over 256 thread-sums
    for (int off = 1; off < 256; off <<= 1) {
        int x = (t >= off) ? s[t - off] : 0;
        __syncthreads();
        s[t] += x;
        __syncthreads();
    }
    if (t == 255) base_sh = atomicAdd(&g_total, s[255]);
    __syncthreads();
    int texcl = s[t] - tsum + base_sh;
    int run = 0;
    #pragma unroll
    for (int k = 0; k < 4; k++) {
        int i = blk + t * 4 + k;
        if (i < n) {
            int o = texcl + run;
            g_start[i]  = o;
            g_cursor[i] = o;
            g_dinv[i]   = rsqrtf((float)(vals[k] + 1));   // +1 self loop
        }
        run += vals[k];
    }
}

__global__ void k_fill(const int* __restrict__ ei, int n_edges, int n_nodes) {
    int e = blockIdx.x * blockDim.x + threadIdx.x;
    if (e < n_edges) {
        int srcv = ei[e];
        int d    = ei[n_edges + e];
        if ((unsigned)d < (unsigned)n_nodes && (unsigned)srcv < (unsigned)n_nodes) {
            int p = atomicAdd(&g_cursor[d], 1);
            g_srcsorted[p] = srcv;
        }
    }
}

// ---------------- TF32 helpers ----------------
__device__ __forceinline__ float to_tf32(float x) {
    uint32_t u;
    asm("cvt.rna.tf32.f32 %0, %1;" : "=r"(u) : "f"(x));
    return __uint_as_float(u);
}

__device__ __forceinline__ void mma_tf32(float c[4], const float a[4], float b0, float b1) {
    uint32_t const* A = reinterpret_cast<uint32_t const*>(a);
    uint32_t B0 = __float_as_uint(b0), B1 = __float_as_uint(b1);
    asm volatile(
        "mma.sync.aligned.m16n8k8.row.col.f32.tf32.tf32.f32 "
        "{%0,%1,%2,%3}, {%4,%5,%6,%7}, {%8,%9}, {%0,%1,%2,%3};"
        : "+f"(c[0]), "+f"(c[1]), "+f"(c[2]), "+f"(c[3])
        : "r"(A[0]), "r"(A[1]), "r"(A[2]), "r"(A[3]), "r"(B0), "r"(B1));
}

// ---------------- TF32 tensor-core GEMM with fused dinv epilogue ----------------
// g_hn[m,n] = g_dinv[m] * sum_k A[m,k]*B[k,n]
// A = external pointer (SRC=0) or g_x2 (SRC=1). BN = N (128 or 64), K multiple of 32.
template <int BN, int SRC>
__global__ void __launch_bounds__(256)
k_mma_dinv(const float* __restrict__ Aext, const float* __restrict__ Bg,
           int M, int K) {
    const float* __restrict__ A = (SRC == 0) ? Aext : g_x2;
    const int KC = 32;
    const int APITCH = KC + 4;        // 36
    const int BPITCH = BN + 8;
    __shared__ float As[128 * APITCH];
    __shared__ float Bs[KC * BPITCH];

    int tid  = threadIdx.x;
    int warp = tid >> 5, lane = tid & 31;
    int wm = warp & 3, wn = warp >> 2;
    const int WNT = BN / 2;
    const int NF  = WNT / 8;
    int g  = lane >> 2, tg = lane & 3;
    int row0 = blockIdx.x * 128;

    float acc[2][NF][4];
    #pragma unroll
    for (int i = 0; i < 2; i++)
        #pragma unroll
        for (int j = 0; j < NF; j++)
            #pragma unroll
            for (int q = 0; q < 4; q++) acc[i][j][q] = 0.0f;

    for (int k0 = 0; k0 < K; k0 += KC) {
        {   // stage A [128 x 32]
            int r = tid >> 3, c = (tid & 7) * 4;
            #pragma unroll
            for (int i = 0; i < 4; i++) {
                int rr = r + i * 32;
                float4 v = make_float4(0.f, 0.f, 0.f, 0.f);
                if (row0 + rr < M)
                    v = *reinterpret_cast<const float4*>(A + (size_t)(row0 + rr) * K + k0 + c);
                v.x = to_tf32(v.x); v.y = to_tf32(v.y);
                v.z = to_tf32(v.z); v.w = to_tf32(v.w);
                *reinterpret_cast<float4*>(&As[rr * APITCH + c]) = v;
            }
        }
        {   // stage B [32 x BN]
            const int TPR = BN / 4;
            int kr = tid / TPR, bc = (tid % TPR) * 4;
            const int KSTEP = 256 / TPR;
            #pragma unroll
            for (int i = 0; i < KC / KSTEP; i++) {
                int kk = kr + i * KSTEP;
                float4 v = *reinterpret_cast<const float4*>(Bg + (size_t)(k0 + kk) * BN + bc);
                v.x = to_tf32(v.x); v.y = to_tf32(v.y);
                v.z = to_tf32(v.z); v.w = to_tf32(v.w);
                *reinterpret_cast<float4*>(&Bs[kk * BPITCH + bc]) = v;
            }
        }
        __syncthreads();

        #pragma unroll
        for (int ks = 0; ks < KC; ks += 8) {
            float a[2][4];
            #pragma unroll
            for (int mf = 0; mf < 2; mf++) {
                int ar = wm * 32 + mf * 16;
                a[mf][0] = As[(ar + g)     * APITCH + ks + tg];
                a[mf][1] = As[(ar + g + 8) * APITCH + ks + tg];
                a[mf][2] = As[(ar + g)     * APITCH + ks + tg + 4];
                a[mf][3] = As[(ar + g + 8) * APITCH + ks + tg + 4];
            }
            #pragma unroll
            for (int nf = 0; nf < NF; nf++) {
                int bn0 = wn * WNT + nf * 8;
                float b0 = Bs[(ks + tg)     * BPITCH + bn0 + g];
                float b1 = Bs[(ks + tg + 4) * BPITCH + bn0 + g];
                #pragma unroll
                for (int mf = 0; mf < 2; mf++)
                    mma_tf32(acc[mf][nf], a[mf], b0, b1);
            }
        }
        __syncthreads();
    }

    #pragma unroll
    for (int mf = 0; mf < 2; mf++) {
        int r0 = row0 + wm * 32 + mf * 16 + g;
        int r1 = r0 + 8;
        float d0 = (r0 < M) ? g_dinv[r0] : 0.f;
        float d1 = (r1 < M) ? g_dinv[r1] : 0.f;
        #pragma unroll
        for (int nf = 0; nf < NF; nf++) {
            int cc = wn * WNT + nf * 8 + tg * 2;
            if (r0 < M) {
                g_hn[(size_t)r0 * BN + cc]     = acc[mf][nf][0] * d0;
                g_hn[(size_t)r0 * BN + cc + 1] = acc[mf][nf][1] * d0;
            }
            if (r1 < M) {
                g_hn[(size_t)r1 * BN + cc]     = acc[mf][nf][2] * d1;
                g_hn[(size_t)r1 * BN + cc + 1] = acc[mf][nf][3] * d1;
            }
        }
    }
}

// ---------------- aggregation: one warp per node, MLP-4 gathers ----------------
// x2[d] = relu( dinv[d]*(hn[d] + sum_{s in N(d)} hn[s]) + b1 )   (F=128)
__global__ void k_agg128(const float* __restrict__ bias, int n_nodes) {
    int warp = (blockIdx.x * blockDim.x + threadIdx.x) >> 5;
    int lane = threadIdx.x & 31;
    if (warp >= n_nodes) return;
    int d = warp;
    const float* hn = g_hn;
    float4 acc = *reinterpret_cast<const float4*>(hn + (size_t)d * 128 + lane * 4);
    float4 acc2 = make_float4(0.f, 0.f, 0.f, 0.f);
    int e = g_start[d], e1 = e + g_count[d];
    for (; e + 4 <= e1; e += 4) {
        int s0 = g_srcsorted[e],     s1 = g_srcsorted[e + 1];
        int s2 = g_srcsorted[e + 2], s3 = g_srcsorted[e + 3];
        float4 v0 = *reinterpret_cast<const float4*>(hn + (size_t)s0 * 128 + lane * 4);
        float4 v1 = *reinterpret_cast<const float4*>(hn + (size_t)s1 * 128 + lane * 4);
        float4 v2 = *reinterpret_cast<const float4*>(hn + (size_t)s2 * 128 + lane * 4);
        float4 v3 = *reinterpret_cast<const float4*>(hn + (size_t)s3 * 128 + lane * 4);
        acc.x += v0.x; acc.y += v0.y; acc.z += v0.z; acc.w += v0.w;
        acc2.x += v1.x; acc2.y += v1.y; acc2.z += v1.z; acc2.w += v1.w;
        acc.x += v2.x; acc.y += v2.y; acc.z += v2.z; acc.w += v2.w;
        acc2.x += v3.x; acc2.y += v3.y; acc2.z += v3.z; acc2.w += v3.w;
    }
    for (; e < e1; e++) {
        int s = g_srcsorted[e];
        float4 v = *reinterpret_cast<const float4*>(hn + (size_t)s * 128 + lane * 4);
        acc.x += v.x; acc.y += v.y; acc.z += v.z; acc.w += v.w;
    }
    acc.x += acc2.x; acc.y += acc2.y; acc.z += acc2.z; acc.w += acc2.w;
    float dv = g_dinv[d];
    float4 bv = *reinterpret_cast<const float4*>(bias + lane * 4);
    float4 o;
    o.x = fmaxf(acc.x * dv + bv.x, 0.f);
    o.y = fmaxf(acc.y * dv + bv.y, 0.f);
    o.z = fmaxf(acc.z * dv + bv.z, 0.f);
    o.w = fmaxf(acc.w * dv + bv.w, 0.f);
    *reinterpret_cast<float4*>(g_x2 + (size_t)d * 128 + lane * 4) = o;
}

// out[d] = dinv[d]*(hn[d] + sum hn[s]) + b2   (F=64, no relu)
__global__ void k_agg64(const float* __restrict__ bias,
                        float* __restrict__ out, int n_nodes) {
    int warp = (blockIdx.x * blockDim.x + threadIdx.x) >> 5;
    int lane = threadIdx.x & 31;
    if (warp >= n_nodes) return;
    int d = warp;
    const float* hn = g_hn;
    float2 acc = *reinterpret_cast<const float2*>(hn + (size_t)d * 64 + lane * 2);
    float2 acc2 = make_float2(0.f, 0.f);
    int e = g_start[d], e1 = e + g_count[d];
    for (; e + 4 <= e1; e += 4) {
        int s0 = g_srcsorted[e],     s1 = g_srcsorted[e + 1];
        int s2 = g_srcsorted[e + 2], s3 = g_srcsorted[e + 3];
        float2 v0 = *reinterpret_cast<const float2*>(hn + (size_t)s0 * 64 + lane * 2);
        float2 v1 = *reinterpret_cast<const float2*>(hn + (size_t)s1 * 64 + lane * 2);
        float2 v2 = *reinterpret_cast<const float2*>(hn + (size_t)s2 * 64 + lane * 2);
        float2 v3 = *reinterpret_cast<const float2*>(hn + (size_t)s3 * 64 + lane * 2);
        acc.x += v0.x; acc.y += v0.y;
        acc2.x += v1.x; acc2.y += v1.y;
        acc.x += v2.x; acc.y += v2.y;
        acc2.x += v3.x; acc2.y += v3.y;
    }
    for (; e < e1; e++) {
        int s = g_srcsorted[e];
        float2 v = *reinterpret_cast<const float2*>(hn + (size_t)s * 64 + lane * 2);
        acc.x += v.x; acc.y += v.y;
    }
    acc.x += acc2.x; acc.y += acc2.y;
    float dv = g_dinv[d];
    float2 bv = *reinterpret_cast<const float2*>(bias + lane * 2);
    float2 o;
    o.x = acc.x * dv + bv.x;
    o.y = acc.y * dv + bv.y;
    *reinterpret_cast<float2*>(out + (size_t)d * 64 + lane * 2) = o;
}

// ---------------- launch ----------------
extern "C" void kernel_launch(void* const* d_in, const int* in_sizes, int n_in,
                              void* d_out, int out_size) {
    const float* x  = (const float*)d_in[0];
    const int*   ei = (const int*)d_in[1];     // int32 [2, E]
    const float* W1 = (const float*)d_in[2];
    const float* b1 = (const float*)d_in[3];
    const float* W2 = (const float*)d_in[4];
    const float* b2 = (const float*)d_in[5];
    float* out = (float*)d_out;

    int n_nodes = in_sizes[0] / FIN;       // 100000
    int n_edges = in_sizes[1] / 2;         // 600000

    int nb_nodes = (n_nodes + 255) / 256;
    int nb_edges = (n_edges + 255) / 256;
    int nb_scan  = (n_nodes + 1023) / 1024;
    int nb_gemm  = (n_nodes + 127) / 128;
    int nb_agg   = (n_nodes * 32 + 255) / 256;

    // ---- CSR build + degrees (4 launches) ----
    k_zero<<<nb_nodes, 256>>>(n_nodes);
    k_hist<<<nb_edges, 256>>>(ei, n_edges, n_nodes);
    k_scan<<<nb_scan, 256>>>(n_nodes);
    k_fill<<<nb_edges, 256>>>(ei, n_edges, n_nodes);

    // ---- layer 1: hn = tf32(x@W1)*dinv ; x2 = relu(dinv*agg + b1) ----
    k_mma_dinv<FHID, 0><<<nb_gemm, 256>>>(x, W1, n_nodes, FIN);
    k_agg128<<<nb_agg, 256>>>(b1, n_nodes);

    // ---- layer 2: hn = tf32(x2@W2)*dinv ; out = dinv*agg + b2 ----
    k_mma_dinv<FOUT, 1><<<nb_gemm, 256>>>(nullptr, W2, n_nodes, FHID);
    k_agg64<<<nb_agg, 256>>>(b2, out, n_nodes);
}